// round 17
// baseline (speedup 1.0000x reference)
#include <cuda_runtime.h>
#include <cuda_fp16.h>
#include <cstdint>

// ---------------------------------------------------------------------------
// AttentionOverride, round 17: R16 + SMEM-staged coalesced V-transpose in the
// QKV epilogue (kills the scattered 2-byte g_vth stores seen in ncu).
// Math bit-identical to R16 -> rel_err must remain 4.998004e-4.
// Output layout: [ a (4M floats) | presentK (4M) | presentV (4M) ]
// ---------------------------------------------------------------------------

namespace {
constexpr int kB  = 4;
constexpr int kS  = 1024;
constexpr int kD  = 1024;
constexpr int kH  = 16;
constexpr int kHD = 64;
constexpr int kM  = kB * kS;  // 4096

constexpr int GKSTR = 72;           // GEMM smem stride (half), BK=64
constexpr int GT2   = 128 * GKSTR;  // one GEMM tile in halves (9216)
constexpr int GEMM_SMEM_BYTES = 4 * GT2 * 2;  // 73728

constexpr int F_KT = 9216;
constexpr int F_VT = 8704;
constexpr int F_V0 = 2 * F_KT;
constexpr int FLASH_SMEM_BYTES = (2 * F_KT + 2 * F_VT) * 2;  // 71680

constexpr int OV_VT = 8704;
constexpr int OV_SMEM_BYTES = 4 * OV_VT * 2;   // 69632

constexpr int PREP_ROUND = kM * kD / 256;             // 16384
constexpr int PREP_WA    = (3 * kD / 32) * (kD / 32); // 3072
constexpr int PREP_WP    = (kD / 32) * (kD / 32);     // 1024
}  // namespace

// scratch (device globals; no allocation allowed)
__device__ int   g_mask_kind;
__device__ uint32_t g_mpack[(size_t)kH * kS * (kS / 32)];
__device__ __half g_qh[(size_t)kM * kD];
__device__ __half g_kh[(size_t)kM * kD];
__device__ __half g_vth[(size_t)kM * kD];       // [BH][64][S]
__device__ __half g_xh[(size_t)kM * kD];
__device__ __half g_oh[(size_t)kM * kD];        // ov term (fp16)
__device__ __half g_ah[(size_t)kM * kD];        // a (fp16) for proj
__device__ __half g_wth[(size_t)3 * kD * kD];
__device__ __half g_pth[(size_t)kD * kD];

// ---------------------------------------------------------------------------
__device__ __forceinline__ void mma16816(float* c, const uint32_t* a,
                                         uint32_t b0, uint32_t b1) {
    asm volatile(
        "mma.sync.aligned.m16n8k16.row.col.f32.f16.f16.f32 "
        "{%0,%1,%2,%3}, {%4,%5,%6,%7}, {%8,%9}, {%0,%1,%2,%3};"
        : "+f"(c[0]), "+f"(c[1]), "+f"(c[2]), "+f"(c[3])
        : "r"(a[0]), "r"(a[1]), "r"(a[2]), "r"(a[3]), "r"(b0), "r"(b1));
}

__device__ __forceinline__ void ldsm_x4(uint32_t& r0, uint32_t& r1,
                                        uint32_t& r2, uint32_t& r3,
                                        uint32_t saddr) {
    asm volatile(
        "ldmatrix.sync.aligned.m8n8.x4.shared.b16 {%0,%1,%2,%3}, [%4];"
        : "=r"(r0), "=r"(r1), "=r"(r2), "=r"(r3) : "r"(saddr));
}

__device__ __forceinline__ uint32_t ex2_h2(uint32_t t) {
    uint32_t r;
    asm volatile("ex2.approx.f16x2 %0, %1;" : "=r"(r) : "r"(t));
    return r;
}

#define CP_ASYNC16(saddr, gptr)                                          \
    asm volatile("cp.async.cg.shared.global [%0], [%1], 16;"             \
                 :: "r"(saddr), "l"(gptr) : "memory")
#define CP_COMMIT() asm volatile("cp.async.commit_group;" ::: "memory")
#define CP_WAIT0()  asm volatile("cp.async.wait_group 0;" ::: "memory")
#define CP_WAIT1()  asm volatile("cp.async.wait_group 1;" ::: "memory")

__device__ __forceinline__ uint32_t smem_u32(const void* p) {
    return (uint32_t)__cvta_generic_to_shared(p);
}

__device__ __forceinline__ uint32_t packh(__half a, __half b) {
    __half2 t = __halves2half2(a, b);
    return *(uint32_t*)&t;
}
__device__ __forceinline__ uint32_t packround(float x, float y) {
    return packh(__float2half_rn(x), __float2half_rn(y));
}
__device__ __forceinline__ float zsum2(uint32_t e) {
    __half2 h = *(__half2*)&e;
    return __half2float(__hadd(h.x, h.y));
}

// ---------------------------------------------------------------------------
__global__ void prep_kernel(const float* __restrict__ x,
                            const float* __restrict__ wa,
                            const float* __restrict__ wp) {
    __shared__ float t[32][33];
    int bid = blockIdx.x;
    int tid = threadIdx.x;
    if (bid < PREP_ROUND) {
        int i = bid * 256 + tid;
        g_xh[i] = __float2half_rn(x[i]);
        return;
    }
    const float* W;
    __half* Th;
    int N, b2;
    if (bid < PREP_ROUND + PREP_WA) {
        b2 = bid - PREP_ROUND;
        W = wa; Th = g_wth; N = 3 * kD;
    } else {
        b2 = bid - PREP_ROUND - PREP_WA;
        W = wp; Th = g_pth; N = kD;
    }
    const int K = kD;
    int nblk = N / 32;
    int n0 = (b2 % nblk) * 32, k0 = (b2 / nblk) * 32;
    int tx = tid & 31, ty = tid >> 5;
#pragma unroll
    for (int j = 0; j < 4; ++j)
        t[ty + j * 8][tx] = W[(size_t)(k0 + ty + j * 8) * N + n0 + tx];
    __syncthreads();
#pragma unroll
    for (int j = 0; j < 4; ++j)
        Th[(size_t)(n0 + ty + j * 8) * K + k0 + tx] =
            __float2half_rn(t[tx][ty + j * 8]);
}

__global__ void detect_mask_kind_kernel(const unsigned int* __restrict__ m) {
    __shared__ int any_gt1, any_not_f32;
    if (threadIdx.x == 0) { any_gt1 = 0; any_not_f32 = 0; }
    __syncthreads();
    int gt1 = 0, nf32 = 0;
    for (int i = threadIdx.x; i < 16384; i += 256) {
        unsigned int w = m[i];
        if (w > 1u) gt1 = 1;
        if (w != 0u && w != 0x3F800000u) nf32 = 1;
    }
    if (gt1)  atomicOr(&any_gt1, 1);
    if (nf32) atomicOr(&any_not_f32, 1);
    __syncthreads();
    if (threadIdx.x == 0)
        g_mask_kind = (!any_gt1) ? 1 : ((!any_not_f32) ? 2 : 0);
}

__global__ void pack_mask_kernel(const void* __restrict__ m) {
    size_t i = (size_t)blockIdx.x * 256 + threadIdx.x;
    const int kind = g_mask_kind;
    bool v;
    if (kind == 0) v = ((const unsigned char*)m)[i] != 0;
    else           v = ((const unsigned int*)m)[i] != 0;
    unsigned int w = __ballot_sync(0xffffffffu, v);
    if ((threadIdx.x & 31) == 0) g_mpack[i >> 5] = w;
}

// ---------------------------------------------------------------------------
// HMMA GEMM, fp16 1-product, BK=64, cp.async double-buffered, ldmatrix.
// mode 1: QKV scatter; V tiles stage the transposed fp16 through SMEM and
// write g_vth with coalesced float4 rows.
// ---------------------------------------------------------------------------
__global__ __launch_bounds__(256, 2) void mma_gemm_kernel(
    const __half* __restrict__ Ah, const __half* __restrict__ Bh,
    const float* __restrict__ bias, float* __restrict__ C,
    int M, int N, int K, int mode,
    float* __restrict__ kout, float* __restrict__ vout)
{
    extern __shared__ __half gsm[];
    __half* sA = gsm;
    __half* sB = gsm + 2 * GT2;

    const int tid = threadIdx.x;
    const int lane = tid & 31;
    const int wid = tid >> 5;
    const int wm = (wid & 3) * 32;
    const int wn = (wid >> 2) * 64;
    const int m0 = blockIdx.y * 128;
    const int n0 = blockIdx.x * 128;
    const int gID = lane >> 2;
    const int tig2 = (lane & 3) * 2;
    const int lt = lane >> 3;
    const int lr = lane & 7;

    const uint32_t sbA = smem_u32(sA);
    const uint32_t sbB = smem_u32(sB);

    auto stage = [&](int c, int buf) {
        size_t ka = (size_t)c * 64;
#pragma unroll
        for (int it = 0; it < 4; ++it) {
            int unit = tid + it * 256;
            int row = unit >> 3, u = unit & 7;
            uint32_t so = (uint32_t)(row * 144 + u * 16) + buf * (GT2 * 2);
            CP_ASYNC16(sbA + so, Ah + (size_t)(m0 + row) * K + ka + u * 8);
            CP_ASYNC16(sbB + so, Bh + (size_t)(n0 + row) * K + ka + u * 8);
        }
        CP_COMMIT();
    };

    float acc[2][8][4] = {};
    const int nchunks = K / 64;

    stage(0, 0);
    for (int c = 0; c < nchunks; ++c) {
        if (c + 1 < nchunks) {
            stage(c + 1, (c + 1) & 1);
            CP_WAIT1();
        } else {
            CP_WAIT0();
        }
        __syncthreads();

        const uint32_t tAb = sbA + (c & 1) * (GT2 * 2);
        const uint32_t tBb = sbB + (c & 1) * (GT2 * 2);
#pragma unroll
        for (int ks = 0; ks < 4; ++ks) {
            const int k0 = ks * 16;
            uint32_t ah[2][4];
#pragma unroll
            for (int mi = 0; mi < 2; ++mi) {
                uint32_t addr = tAb + (uint32_t)(
                    ((wm + mi * 16 + (lt & 1) * 8 + lr) * GKSTR +
                     k0 + (lt >> 1) * 8) * 2);
                ldsm_x4(ah[mi][0], ah[mi][1], ah[mi][2], ah[mi][3], addr);
            }
#pragma unroll
            for (int ntp = 0; ntp < 4; ++ntp) {
                uint32_t addr = tBb + (uint32_t)(
                    ((wn + ntp * 16 + (lt >> 1) * 8 + lr) * GKSTR +
                     k0 + (lt & 1) * 8) * 2);
                uint32_t b00, b01, b10, b11;
                ldsm_x4(b00, b01, b10, b11, addr);
                mma16816(acc[0][2 * ntp],     ah[0], b00, b01);
                mma16816(acc[1][2 * ntp],     ah[1], b00, b01);
                mma16816(acc[0][2 * ntp + 1], ah[0], b10, b11);
                mma16816(acc[1][2 * ntp + 1], ah[1], b10, b11);
            }
        }
        __syncthreads();
    }

    const int sec_cta = (mode == 1) ? (n0 >> 10) : -1;
    __half* sT = gsm;  // V-transpose staging [128 n][136 m], free after loop

#pragma unroll
    for (int mi = 0; mi < 2; ++mi) {
#pragma unroll
        for (int nt = 0; nt < 8; ++nt) {
            int m = m0 + wm + mi * 16 + gID;
            int n = n0 + wn + nt * 8 + tig2;
            float b0 = bias[n], b1 = bias[n + 1];
            float v0 = acc[mi][nt][0] + b0;
            float v1 = acc[mi][nt][1] + b1;
            float v2 = acc[mi][nt][2] + b0;
            float v3 = acc[mi][nt][3] + b1;
            if (mode == 0) {
                *(float2*)&C[(size_t)m * N + n] = make_float2(v0, v1);
                *(float2*)&C[(size_t)(m + 8) * N + n] = make_float2(v2, v3);
            } else {
                int e = n & 1023;
                int h = e >> 6;
                int d = e & 63;
#pragma unroll
                for (int rr = 0; rr < 2; ++rr) {
                    int mm = m + rr * 8;
                    int bb = mm >> 10;
                    int s = mm & 1023;
                    size_t idx = (((size_t)(bb * kH + h)) * kS + s) * kHD + d;
                    float p0 = rr ? v2 : v0, p1 = rr ? v3 : v1;
                    if (sec_cta == 0) {
                        *(uint32_t*)&g_qh[idx] = packround(p0, p1);
                    } else if (sec_cta == 1) {
                        *(float2*)&kout[idx] = make_float2(p0, p1);
                        *(uint32_t*)&g_kh[idx] = packround(p0, p1);
                    } else {
                        *(float2*)&vout[idx] = make_float2(p0, p1);
                        int nn = wn + nt * 8 + tig2;          // n - n0
                        int mml = wm + mi * 16 + gID + rr * 8; // m - m0
                        sT[nn * 136 + mml] = __float2half_rn(p0);
                        sT[(nn + 1) * 136 + mml] = __float2half_rn(p1);
                    }
                }
            }
        }
    }

    if (sec_cta == 2) {
        __syncthreads();
        const int b = m0 >> 10;
        const int s0 = m0 & 1023;
#pragma unroll
        for (int i = tid; i < 128 * 16; i += 256) {
            int nn = i >> 4, u = i & 15;
            int e = (n0 + nn) & 1023;
            int hh = e >> 6;
            int d = e & 63;
            size_t dst = ((size_t)(b * kH + hh) * kHD + d) * kS + s0 + u * 8;
            *(float4*)&g_vth[dst] = *(float4*)&sT[nn * 136 + u * 8];
        }
    }
}

// ---------------------------------------------------------------------------
// OV kernel (batch-shared, bit-packed mask, ldmatrix); writes fp16 g_oh.
// ---------------------------------------------------------------------------
__global__ __launch_bounds__(256, 2) void ov_kernel(
    const float* __restrict__ ov)
{
    extern __shared__ __half sV[];
    const int tid = threadIdx.x, lane = tid & 31, wid = tid >> 5;
    const int gID = lane >> 2, tig2 = (lane & 3) * 2;
    const int lt = lane >> 3, lr = lane & 7;
    const int h = blockIdx.y, q0 = blockIdx.x * 64;
    const int qsub = wid & 3;
    const int dhalf = wid >> 2;
    const int qr0 = q0 + qsub * 16 + gID, qr1 = qr0 + 8;
    const size_t mr0 = ((size_t)h * kS + qr0) * kS;
    const size_t mr1 = ((size_t)h * kS + qr1) * kS;
    const size_t wb0 = ((size_t)h * kS + qr0) * 32;
    const size_t wb1 = ((size_t)h * kS + qr1) * 32;
    const uint32_t sbV = smem_u32(sV);

    float o[4][4][4] = {};

    for (int kc = 0; kc < 8; ++kc) {
#pragma unroll
        for (int bb = 0; bb < 4; ++bb) {
            const size_t bhT = (size_t)(bb * kH + h) * kHD;
#pragma unroll
            for (int it = 0; it < 2; ++it) {
                int unit = tid + it * 256;
                int row = unit >> 3, u = (unit & 7) * 16;
                *(float4*)&sV[bb * OV_VT + row * 136 + u] =
                    *(const float4*)&g_vth[(bhT + row) * kS + kc * 128 + u];
                *(float4*)&sV[bb * OV_VT + row * 136 + u + 8] =
                    *(const float4*)&g_vth[(bhT + row) * kS + kc * 128 + u + 8];
            }
        }
        __syncthreads();

        uint32_t w0[4], w1[4];
#pragma unroll
        for (int j = 0; j < 4; ++j) {
            w0[j] = g_mpack[wb0 + kc * 4 + j];
            w1[j] = g_mpack[wb1 + kc * 4 + j];
        }

#pragma unroll
        for (int ks = 0; ks < 8; ++ks) {
            size_t kg = (size_t)kc * 128 + ks * 16 + tig2;
            int wd = ks >> 1;
            int bp = (ks & 1) * 16 + tig2;
            float2 v00 = *(const float2*)&ov[mr0 + kg];
            float2 v02 = *(const float2*)&ov[mr0 + kg + 8];
            float2 v10 = *(const float2*)&ov[mr1 + kg];
            float2 v12 = *(const float2*)&ov[mr1 + kg + 8];
            uint32_t ah[4];
            ah[0] = packround(((w0[wd] >> bp) & 1) ? v00.x : 0.f,
                              ((w0[wd] >> (bp + 1)) & 1) ? v00.y : 0.f);
            ah[1] = packround(((w1[wd] >> bp) & 1) ? v10.x : 0.f,
                              ((w1[wd] >> (bp + 1)) & 1) ? v10.y : 0.f);
            ah[2] = packround(((w0[wd] >> (bp + 8)) & 1) ? v02.x : 0.f,
                              ((w0[wd] >> (bp + 9)) & 1) ? v02.y : 0.f);
            ah[3] = packround(((w1[wd] >> (bp + 8)) & 1) ? v12.x : 0.f,
                              ((w1[wd] >> (bp + 9)) & 1) ? v12.y : 0.f);
#pragma unroll
            for (int bb = 0; bb < 4; ++bb)
#pragma unroll
                for (int dnp = 0; dnp < 2; ++dnp) {
                    uint32_t addr = sbV + (uint32_t)((bb * OV_VT +
                        (dhalf * 32 + dnp * 16 + (lt >> 1) * 8 + lr) * 136 +
                        ks * 16 + (lt & 1) * 8) * 2);
                    uint32_t b00, b01, b10, b11;
                    ldsm_x4(b00, b01, b10, b11, addr);
                    mma16816(o[bb][2 * dnp],     ah, b00, b01);
                    mma16816(o[bb][2 * dnp + 1], ah, b10, b11);
                }
        }
        __syncthreads();
    }

#pragma unroll
    for (int bb = 0; bb < 4; ++bb)
#pragma unroll
        for (int dn = 0; dn < 4; ++dn) {
            int d = h * kHD + dhalf * 32 + dn * 8 + tig2;
            *(uint32_t*)&g_oh[(size_t)(bb * kS + qr0) * kD + d] =
                packround(o[bb][dn][0], o[bb][dn][1]);
            *(uint32_t*)&g_oh[(size_t)(bb * kS + qr1) * kD + d] =
                packround(o[bb][dn][2], o[bb][dn][3]);
        }
}

// ---------------------------------------------------------------------------
// Flash kernel (unchanged from R16).
// ---------------------------------------------------------------------------
__global__ __launch_bounds__(256, 2) void flash_kernel()
{
    extern __shared__ __half fsm[];
    __half* sK = fsm;
    __half* sV = fsm + F_V0;

    const int tid = threadIdx.x, lane = tid & 31, wid = tid >> 5;
    const int gID = lane >> 2, tig2 = (lane & 3) * 2;
    const int lt = lane >> 3, lr = lane & 7;
    const int b = blockIdx.z, h = blockIdx.y;
    const int qt = (int)gridDim.x - 1 - (int)blockIdx.x;
    const int q0 = qt * 128;
    const int wq = wid * 16;
    const size_t bh = (size_t)(b * kH + h) * kS * kHD;
    const size_t bhT = (size_t)(b * kH + h) * kHD;
    const uint32_t sbK = smem_u32(sK);
    const uint32_t sbV = smem_u32(sV);
    const float CEXP = 0.18033688f;

    auto stageKV = [&](int c, int buf) {
#pragma unroll
        for (int it = 0; it < 4; ++it) {
            int unit = tid + it * 256;
            int row = unit >> 3, u = unit & 7;
            uint32_t so = (uint32_t)(row * 144 + u * 16) + buf * (F_KT * 2);
            CP_ASYNC16(sbK + so,
                       g_kh + bh + (size_t)(c * 128 + row) * kHD + u * 8);
        }
#pragma unroll
        for (int it = 0; it < 4; ++it) {
            int unit = tid + it * 256;
            int row = unit >> 4, u16 = unit & 15;
            uint32_t so = (uint32_t)(row * 272 + u16 * 16) + buf * (F_VT * 2);
            CP_ASYNC16(sbV + so,
                       g_vth + (bhT + row) * kS + (size_t)c * 128 + u16 * 8);
        }
        CP_COMMIT();
    };

#pragma unroll
    for (int it = 0; it < 4; ++it) {
        int unit = tid + it * 256;
        int row = unit >> 3, u = (unit & 7) * 8;
        *(float4*)&sK[row * 72 + u] =
            *(const float4*)&g_qh[bh + (size_t)(q0 + row) * kHD + u];
    }
    __syncthreads();
    uint32_t qf[4][4];
#pragma unroll
    for (int ks = 0; ks < 4; ++ks) {
        uint32_t addr = sbK + (uint32_t)(
            ((wq + (lt & 1) * 8 + lr) * 72 + ks * 16 + (lt >> 1) * 8) * 2);
        ldsm_x4(qf[ks][0], qf[ks][1], qf[ks][2], qf[ks][3], addr);
    }
    __syncthreads();

    stageKV(0, 0);

    float o[8][4] = {};
    float Z0 = 0.f, Z1 = 0.f;
    const int qr0 = q0 + wq + gID, qr1 = qr0 + 8;
    const size_t wb0 = ((size_t)h * kS + qr0) * 32;
    const size_t wb1 = ((size_t)h * kS + qr1) * 32;

    for (int kc = 0; kc <= qt; ++kc) {
        if (kc + 1 <= qt) {
            stageKV(kc + 1, (kc + 1) & 1);
            CP_WAIT1();
        } else {
            CP_WAIT0();
        }
        __syncthreads();

        const uint32_t tKb = sbK + (kc & 1) * (F_KT * 2);
        const uint32_t tVb = sbV + (kc & 1) * (F_VT * 2);
        const bool diag = (kc == qt);

        for (int qq = 0; qq < 4; ++qq) {
            float sa[4][4] = {};
#pragma unroll
            for (int ks = 0; ks < 4; ++ks)
#pragma unroll
                for (int ntp = 0; ntp < 2; ++ntp) {
                    uint32_t addr = tKb + (uint32_t)(
                        ((qq * 32 + ntp * 16 + (lt >> 1) * 8 + lr) * 72 +
                         ks * 16 + (lt & 1) * 8) * 2);
                    uint32_t b00, b01, b10, b11;
                    ldsm_x4(b00, b01, b10, b11, addr);
                    mma16816(sa[2 * ntp],     qf[ks], b00, b01);
                    mma16816(sa[2 * ntp + 1], qf[ks], b10, b11);
                }

            uint32_t mw0 = g_mpack[wb0 + kc * 4 + qq];
            uint32_t mw1 = g_mpack[wb1 + kc * 4 + qq];
            uint32_t ehr0[4], ehr1[4];
            if (diag) {
#pragma unroll
                for (int nt = 0; nt < 4; ++nt) {
                    int kg = kc * 128 + qq * 32 + nt * 8 + tig2;
                    int bp = nt * 8 + tig2;
                    __half2 t0 = __floats2half2_rn(sa[nt][0] * CEXP,
                                                   sa[nt][1] * CEXP);
                    __half2 t1 = __floats2half2_rn(sa[nt][2] * CEXP,
                                                   sa[nt][3] * CEXP);
                    uint32_t e0 = ex2_h2(*(uint32_t*)&t0);
                    uint32_t e1 = ex2_h2(*(uint32_t*)&t1);
                    uint32_t ca0 = (kg <= qr0 ? 0x0000FFFFu : 0u) |
                                   (kg + 1 <= qr0 ? 0xFFFF0000u : 0u);
                    uint32_t ca1 = (kg <= qr1 ? 0x0000FFFFu : 0u) |
                                   (kg + 1 <= qr1 ? 0xFFFF0000u : 0u);
                    e0 &= ca0;
                    e1 &= ca1;
                    Z0 += zsum2(e0);
                    Z1 += zsum2(e1);
                    uint32_t mm0 = (((mw0 >> bp) & 1) ? 0x0000FFFFu : 0u) |
                                   (((mw0 >> (bp + 1)) & 1) ? 0xFFFF0000u : 0u);
                    uint32_t mm1 = (((mw1 >> bp) & 1) ? 0x0000FFFFu : 0u) |
                                   (((mw1 >> (bp + 1)) & 1) ? 0xFFFF0000u : 0u);
                    ehr0[nt] = e0 & ~mm0;
                    ehr1[nt] = e1 & ~mm1;
                }
            } else {
#pragma unroll
                for (int nt = 0; nt < 4; ++nt) {
                    int bp = nt * 8 + tig2;
                    __half2 t0 = __floats2half2_rn(sa[nt][0] * CEXP,
                                                   sa[nt][1] * CEXP);
                    __half2 t1 = __floats2half2_rn(sa[nt][2] * CEXP,
                                                   sa[nt][3] * CEXP);
                    uint32_t e0 = ex2_h2(*(uint32_t*)&t0);
                    uint32_t e1 = ex2_h2(*(uint32_t*)&t1);
                    Z0 += zsum2(e0);
                    Z1 += zsum2(e1);
                    uint32_t mm0 = (((mw0 >> bp) & 1) ? 0x0000FFFFu : 0u) |
                                   (((mw0 >> (bp + 1)) & 1) ? 0xFFFF0000u : 0u);
                    uint32_t mm1 = (((mw1 >> bp) & 1) ? 0x0000FFFFu : 0u) |
                                   (((mw1 >> (bp + 1)) & 1) ? 0xFFFF0000u : 0u);
                    ehr0[nt] = e0 & ~mm0;
                    ehr1[nt] = e1 & ~mm1;
                }
            }
#pragma unroll
            for (int k2 = 0; k2 < 2; ++k2) {
                uint32_t ah[4] = {ehr0[2 * k2], ehr1[2 * k2],
                                  ehr0[2 * k2 + 1], ehr1[2 * k2 + 1]};
#pragma unroll
                for (int dnp = 0; dnp < 4; ++dnp) {
                    uint32_t addr = tVb + (uint32_t)(
                        ((dnp * 16 + (lt >> 1) * 8 + lr) * 136 +
                         qq * 32 + k2 * 16 + (lt & 1) * 8) * 2);
                    uint32_t b00, b01, b10, b11;
                    ldsm_x4(b00, b01, b10, b11, addr);
                    mma16816(o[2 * dnp],     ah, b00, b01);
                    mma16816(o[2 * dnp + 1], ah, b10, b11);
                }
            }
        }
        __syncthreads();
    }

    Z0 += __shfl_xor_sync(0xffffffffu, Z0, 1);
    Z0 += __shfl_xor_sync(0xffffffffu, Z0, 2);
    Z1 += __shfl_xor_sync(0xffffffffu, Z1, 1);
    Z1 += __shfl_xor_sync(0xffffffffu, Z1, 2);
    float i0 = 1.f / Z0, i1 = 1.f / Z1;

#pragma unroll
    for (int dn = 0; dn < 8; ++dn) {
        int d = h * kHD + dn * 8 + tig2;
        size_t r0 = (size_t)(b * kS + qr0) * kD + d;
        size_t r1 = (size_t)(b * kS + qr1) * kD + d;
        uint32_t pw0 = *(const uint32_t*)&g_oh[r0];
        uint32_t pw1 = *(const uint32_t*)&g_oh[r1];
        float2 p0 = __half22float2(*(__half2*)&pw0);
        float2 p1 = __half22float2(*(__half2*)&pw1);
        *(uint32_t*)&g_ah[r0] =
            packround(p0.x + o[dn][0] * i0, p0.y + o[dn][1] * i0);
        *(uint32_t*)&g_ah[r1] =
            packround(p1.x + o[dn][2] * i1, p1.y + o[dn][3] * i1);
    }
}

// ---------------------------------------------------------------------------
extern "C" void kernel_launch(void* const* d_in, const int* in_sizes, int n_in,
                              void* d_out, int out_size)
{
    const float* x       = (const float*)d_in[0];
    const float* w_attn  = (const float*)d_in[1];
    const float* b_attn  = (const float*)d_in[2];
    const float* w_proj  = (const float*)d_in[3];
    const float* b_proj  = (const float*)d_in[4];
    const float* ov      = (const float*)d_in[5];
    const void*  msk     = (const void*)d_in[6];

    float* out = (float*)d_out;
    float* presentK = out + (size_t)kM * kD;
    float* presentV = presentK + (size_t)kB * kH * kS * kHD;

    __half *xh, *ah, *wth, *pth;
    cudaGetSymbolAddress((void**)&xh, g_xh);
    cudaGetSymbolAddress((void**)&ah, g_ah);
    cudaGetSymbolAddress((void**)&wth, g_wth);
    cudaGetSymbolAddress((void**)&pth, g_pth);

    cudaFuncSetAttribute(mma_gemm_kernel,
                         cudaFuncAttributeMaxDynamicSharedMemorySize,
                         GEMM_SMEM_BYTES);
    cudaFuncSetAttribute(flash_kernel,
                         cudaFuncAttributeMaxDynamicSharedMemorySize,
                         FLASH_SMEM_BYTES);
    cudaFuncSetAttribute(ov_kernel,
                         cudaFuncAttributeMaxDynamicSharedMemorySize,
                         OV_SMEM_BYTES);

    // 0) mask classification + bit-pack + fused operand prep
    detect_mask_kind_kernel<<<1, 256>>>((const unsigned int*)msk);
    pack_mask_kernel<<<(kH * kS * kS) / 256, 256>>>(msk);
    prep_kernel<<<PREP_ROUND + PREP_WA + PREP_WP, 256>>>(x, w_attn, w_proj);

    // 1) QKV GEMM -> present fp32 + q/k fp16 + V transposed fp16 (staged)
    mma_gemm_kernel<<<dim3(3 * kD / 128, kM / 128), 256, GEMM_SMEM_BYTES>>>(
        xh, wth, b_attn, nullptr, kM, 3 * kD, kD, 1, presentK, presentV);

    // 2) override term -> g_oh (fp16, batch-shared)
    ov_kernel<<<dim3(kS / 64, kH), 256, OV_SMEM_BYTES>>>(ov);

    // 3) flash: adds softmax term, writes fp16 a directly
    flash_kernel<<<dim3(kS / 128, kH, kB), 256, FLASH_SMEM_BYTES>>>();

    // 4) output projection
    mma_gemm_kernel<<<dim3(kD / 128, kM / 128), 256, GEMM_SMEM_BYTES>>>(
        ah, pth, b_proj, out, kM, kD, kD, 0, nullptr, nullptr);
}